// round 17
// baseline (speedup 1.0000x reference)
#include <cuda_runtime.h>
#include <cuda_bf16.h>
#include <cstdint>
#include <mma.h>

using namespace nvcuda;

#define B_      8
#define C_      256
#define H_      128
#define W_      128
#define HW_     (H_ * W_)
#define GROUPS_ 32
#define CPG_    8
#define EPS_    1e-5f

typedef unsigned long long u64;
typedef __nv_bfloat16 bf16;

// ---------------------------------------------------------------------------
// Scratch
// ---------------------------------------------------------------------------
__device__ float  g_Yq[(size_t)B_ * C_ * HW_];
__device__ float  g_Yk[(size_t)B_ * C_ * HW_];
__device__ __align__(16) bf16 g_Wbh[2][C_ * C_];   // bf16(v)
__device__ __align__(16) bf16 g_Wbl[2][C_ * C_];   // bf16(v - hi)
__device__ float  g_psum[2][B_][GROUPS_][2];
__device__ float2 g_stats[2][B_][GROUPS_];

// ---------------------------------------------------------------------------
// small kernels
// ---------------------------------------------------------------------------
__global__ void init_kernel() { ((float*)g_psum)[threadIdx.x] = 0.f; }

__global__ __launch_bounds__(256) void wprep_kernel(
    const float* __restrict__ Wq, const float* __restrict__ Wk)
{
    const int i = blockIdx.x * 256 + threadIdx.x;
    const int t = i >> 16, j = i & 65535;
    const float v  = (t ? Wk : Wq)[j];
    const bf16 hi = __float2bfloat16_rn(v);
    const bf16 lo = __float2bfloat16_rn(v - __bfloat162float(hi));
    g_Wbh[t][j] = hi;
    g_Wbl[t][j] = lo;
}

__global__ void gn_finalize() {
    const int t = threadIdx.x;
    const int te = t >> 8, b = (t >> 5) & 7, g = t & 31;
    const float inv = 1.0f / (float)(CPG_ * HW_);
    float mu  = g_psum[te][b][g][0] * inv;
    float var = g_psum[te][b][g][1] * inv - mu * mu;
    g_stats[te][b][g] = make_float2(mu, rsqrtf(fmaxf(var, 0.f) + EPS_));
}

// ---------------------------------------------------------------------------
// Conv: WMMA bf16 m16n16k16, 3-term split, double-buffered (proven R15/R16)
// ---------------------------------------------------------------------------
#define OFF_AL  5120
#define OFF_BH  10240
#define OFF_BL  14592
#define STG_EL  18944
#define CONV_SMEM (STG_EL * 2 * 2)

using FragA  = wmma::fragment<wmma::matrix_a, 16, 16, 16, bf16, wmma::row_major>;
using FragB  = wmma::fragment<wmma::matrix_b, 16, 16, 16, bf16, wmma::row_major>;
using FragAc = wmma::fragment<wmma::matrix_a, 16, 16, 16, bf16, wmma::col_major>;
using FragBc = wmma::fragment<wmma::matrix_b, 16, 16, 16, bf16, wmma::col_major>;
using FragC  = wmma::fragment<wmma::accumulator, 16, 16, 16, float>;

__global__ __launch_bounds__(512, 1) void conv_tc_kernel(
    const float* __restrict__ X0, const float* __restrict__ X1)
{
    extern __shared__ __align__(16) bf16 smh[];
    __shared__ float sg[16][2];

    const int tid = threadIdx.x;
    const int wid = tid >> 5;
    const int warp_m = wid & 3;
    const int warp_n = wid >> 2;
    const int o0 = blockIdx.x * 128;
    const int s0 = blockIdx.y * 128;
    const int which = blockIdx.z >> 3;
    const int b  = blockIdx.z & 7;

    const float*  X  = which ? X1 : X0;
    float* __restrict__ Y = which ? g_Yk : g_Yq;
    const bf16* Wbh = g_Wbh[which];
    const bf16* Wbl = g_Wbl[which];

    FragC acc[2][2];
#pragma unroll
    for (int tm = 0; tm < 2; tm++)
#pragma unroll
        for (int tn = 0; tn < 2; tn++) wmma::fill_fragment(acc[tm][tn], 0.f);

    const int wrow = tid >> 2, wseg = (tid & 3) * 8;
    const int xrow = tid >> 4, xseg = (tid & 15) * 8;

    uint4 whv, wlv;
    float xv[8];
    {
        whv = *(const uint4*)&Wbh[(size_t)(o0 + wrow) * C_ + wseg];
        wlv = *(const uint4*)&Wbl[(size_t)(o0 + wrow) * C_ + wseg];
        const float* xp = X + ((size_t)b * C_ + xrow) * HW_ + s0 + xseg;
        *(float4*)&xv[0] = *(const float4*)xp;
        *(float4*)&xv[4] = *(const float4*)(xp + 4);
    }
    {
        *(uint4*)&smh[wrow * 40 + wseg]          = whv;
        *(uint4*)&smh[OFF_AL + wrow * 40 + wseg] = wlv;
        __align__(16) bf16 hh[8], ll[8];
#pragma unroll
        for (int j = 0; j < 8; j++) {
            hh[j] = __float2bfloat16_rn(xv[j]);
            ll[j] = __float2bfloat16_rn(xv[j] - __bfloat162float(hh[j]));
        }
        *(uint4*)&smh[OFF_BH + xrow * 136 + xseg] = *(uint4*)hh;
        *(uint4*)&smh[OFF_BL + xrow * 136 + xseg] = *(uint4*)ll;
    }
    if (tid < 32) ((float*)sg)[tid] = 0.f;
    __syncthreads();

    for (int ch = 0; ch < 8; ch++) {
        const bf16* cb = smh + (ch & 1) * STG_EL;

        if (ch < 7) {
            const int c0 = (ch + 1) * 32;
            whv = *(const uint4*)&Wbh[(size_t)(o0 + wrow) * C_ + c0 + wseg];
            wlv = *(const uint4*)&Wbl[(size_t)(o0 + wrow) * C_ + c0 + wseg];
            const float* xp = X + ((size_t)b * C_ + c0 + xrow) * HW_ + s0 + xseg;
            *(float4*)&xv[0] = *(const float4*)xp;
            *(float4*)&xv[4] = *(const float4*)(xp + 4);
        }

#pragma unroll
        for (int t = 0; t < 2; t++) {
            FragA ah[2], al[2];
#pragma unroll
            for (int tm = 0; tm < 2; tm++) {
                const int ao = (warp_m * 32 + tm * 16) * 40 + t * 16;
                wmma::load_matrix_sync(ah[tm], cb + ao, 40);
                wmma::load_matrix_sync(al[tm], cb + OFF_AL + ao, 40);
            }
#pragma unroll
            for (int tn = 0; tn < 2; tn++) {
                FragB bh, bl;
                const int bo = (t * 16) * 136 + warp_n * 32 + tn * 16;
                wmma::load_matrix_sync(bh, cb + OFF_BH + bo, 136);
                wmma::load_matrix_sync(bl, cb + OFF_BL + bo, 136);
#pragma unroll
                for (int tm = 0; tm < 2; tm++) {
                    wmma::mma_sync(acc[tm][tn], ah[tm], bh, acc[tm][tn]);
                    wmma::mma_sync(acc[tm][tn], ah[tm], bl, acc[tm][tn]);
                    wmma::mma_sync(acc[tm][tn], al[tm], bh, acc[tm][tn]);
                }
            }
        }

        if (ch < 7) {
            bf16* nb = smh + ((ch + 1) & 1) * STG_EL;
            *(uint4*)&nb[wrow * 40 + wseg]          = whv;
            *(uint4*)&nb[OFF_AL + wrow * 40 + wseg] = wlv;
            __align__(16) bf16 hh[8], ll[8];
#pragma unroll
            for (int j = 0; j < 8; j++) {
                hh[j] = __float2bfloat16_rn(xv[j]);
                ll[j] = __float2bfloat16_rn(xv[j] - __bfloat162float(hh[j]));
            }
            *(uint4*)&nb[OFF_BH + xrow * 136 + xseg] = *(uint4*)hh;
            *(uint4*)&nb[OFF_BL + xrow * 136 + xseg] = *(uint4*)ll;
        }
        __syncthreads();
    }

    float* stg = (float*)smh;
    float s = 0.f, ss = 0.f;
    const int row = tid >> 2, cq = (tid & 3) * 16;
#pragma unroll
    for (int h = 0; h < 2; h++) {
        __syncthreads();
        if ((warp_n >> 1) == h) {
#pragma unroll
            for (int tm = 0; tm < 2; tm++)
#pragma unroll
                for (int tn = 0; tn < 2; tn++)
                    wmma::store_matrix_sync(
                        &stg[(warp_m * 32 + tm * 16) * 68 + (warp_n & 1) * 32 + tn * 16],
                        acc[tm][tn], 68, wmma::mem_row_major);
        }
        __syncthreads();
        float* Yp = Y + ((size_t)b * C_ + o0 + row) * HW_ + s0 + h * 64 + cq;
#pragma unroll
        for (int j = 0; j < 4; j++) {
            float4 v = *(const float4*)&stg[row * 68 + cq + 4 * j];
            *(float4*)(Yp + 4 * j) = v;
            s  += v.x + v.y + v.z + v.w;
            ss += v.x * v.x + v.y * v.y + v.z * v.z + v.w * v.w;
        }
    }
    atomicAdd(&sg[row >> 3][0], s);
    atomicAdd(&sg[row >> 3][1], ss);
    __syncthreads();
    if (tid < 32)
        atomicAdd(&g_psum[which][b][(o0 >> 3) + (tid >> 1)][tid & 1], sg[tid >> 1][tid & 1]);
}

// ---------------------------------------------------------------------------
// Attention v2: WMMA bf16 3-term split, OCCUPANCY 2 (109.6KB smem, 256 thr).
//   k hi/lo resident [256][72]; q STREAMED in 8 double-buffered 32-c chunks;
//   A overlays dead q-buffer; O computed in 4 c-quarters staged through the
//   dead S region. All fragment orientations identical to proven R16 kernel.
// smem (bf16 el idx unless noted):
//   KHI 0        [256][72]       KLO 18432
//   QB  36864    [2][hi/lo][32][72] (stride: buf 4608, lo +2304)
//   AHI 36864    [64][72]        ALO 41472        (overlays QB)
//   SF  f32 idx 23040  [64][68]  (bytes 92160..109568; reused as Ostg)
// ---------------------------------------------------------------------------
#define KHI   0
#define KLO   18432
#define QB0   36864
#define AHI   36864
#define ALO   41472
#define SF_IX 23040
#define ATTN_SMEM 109568

__global__ __launch_bounds__(256, 2) void attn_kernel(
    const float* __restrict__ xlow,
    const float* __restrict__ gq, const float* __restrict__ bq,
    const float* __restrict__ gk, const float* __restrict__ bk,
    float* __restrict__ out)
{
    extern __shared__ __align__(16) char smc[];
    bf16*  smb = (bf16*)smc;
    float* Sf  = (float*)smc + SF_IX;      // [64][68] f32; later Ostg quarter

    const int n  = blockIdx.x;
    const int b  = n >> 8;
    const int ph = (n >> 4) & 15;
    const int pw = n & 15;
    const int tid = threadIdx.x;
    const int wid = tid >> 5;
    const size_t pbase = (size_t)b * C_ * HW_ + (size_t)(ph * 8) * W_ + pw * 8;

    const int cl = tid >> 3, il = tid & 7;         // loader coords
    const size_t lbase = pbase + (size_t)il * W_;

    // ---- phase 1: load + normalize + split k (resident) ----
#pragma unroll
    for (int pass = 0; pass < 8; pass++) {
        const int c = pass * 32 + cl;
        const float2 st = g_stats[1][b][c >> 3];
        const float ak = st.y * __ldg(gk + c), ck = __ldg(bk + c) - st.x * ak;
        const float* src = g_Yk + lbase + (size_t)c * HW_;
        float vk[8];
        *(float4*)&vk[0] = *(const float4*)src;
        *(float4*)&vk[4] = *(const float4*)(src + 4);
        __align__(16) bf16 hh[8], ll[8];
#pragma unroll
        for (int j = 0; j < 8; j++) {
            const float k = vk[j] * ak + ck;
            hh[j] = __float2bfloat16_rn(k);
            ll[j] = __float2bfloat16_rn(k - __bfloat162float(hh[j]));
        }
        *(uint4*)&smb[KHI + c * 72 + il * 8] = *(uint4*)hh;
        *(uint4*)&smb[KLO + c * 72 + il * 8] = *(uint4*)ll;
    }

    // ---- q chunk 0 into buf 0 ----
    float qv[8]; float aq, cq0;
    {
        const int c = cl;
        const float2 st = g_stats[0][b][c >> 3];
        aq = st.y * __ldg(gq + c); cq0 = __ldg(bq + c) - st.x * aq;
        const float* src = g_Yq + lbase + (size_t)c * HW_;
        *(float4*)&qv[0] = *(const float4*)src;
        *(float4*)&qv[4] = *(const float4*)(src + 4);
    }
    {
        __align__(16) bf16 hh[8], ll[8];
#pragma unroll
        for (int j = 0; j < 8; j++) {
            const float q = qv[j] * aq + cq0;
            hh[j] = __float2bfloat16_rn(q);
            ll[j] = __float2bfloat16_rn(q - __bfloat162float(hh[j]));
        }
        *(uint4*)&smb[QB0 + cl * 72 + il * 8]        = *(uint4*)hh;
        *(uint4*)&smb[QB0 + 2304 + cl * 72 + il * 8] = *(uint4*)ll;
    }
    __syncthreads();

    // ---- phase 2: S = q^T k, q streamed (8 warps: warp_p=wid>>2, warp_pp=wid&3) ----
    const int warp_p = wid >> 2, warp_pp = wid & 3;
    FragC accS[2];
    wmma::fill_fragment(accS[0], 0.f);
    wmma::fill_fragment(accS[1], 0.f);

    for (int ch = 0; ch < 8; ch++) {
        if (ch < 7) {   // prefetch next q chunk into regs
            const int c = (ch + 1) * 32 + cl;
            const float2 st = g_stats[0][b][c >> 3];
            aq = st.y * __ldg(gq + c); cq0 = __ldg(bq + c) - st.x * aq;
            const float* src = g_Yq + lbase + (size_t)c * HW_;
            *(float4*)&qv[0] = *(const float4*)src;
            *(float4*)&qv[4] = *(const float4*)(src + 4);
        }
        const bf16* qb = smb + QB0 + (ch & 1) * 4608;
#pragma unroll
        for (int cs = 0; cs < 2; cs++) {
            FragAc qh_f[2], ql_f[2];
#pragma unroll
            for (int tp = 0; tp < 2; tp++) {
                const int qo = cs * 16 * 72 + warp_p * 32 + tp * 16;
                wmma::load_matrix_sync(qh_f[tp], qb + qo, 72);
                wmma::load_matrix_sync(ql_f[tp], qb + 2304 + qo, 72);
            }
            FragB kh_f, kl_f;
            const int crow = ch * 32 + cs * 16;
            wmma::load_matrix_sync(kh_f, smb + KHI + crow * 72 + warp_pp * 16, 72);
            wmma::load_matrix_sync(kl_f, smb + KLO + crow * 72 + warp_pp * 16, 72);
#pragma unroll
            for (int tp = 0; tp < 2; tp++) {
                wmma::mma_sync(accS[tp], qh_f[tp], kh_f, accS[tp]);
                wmma::mma_sync(accS[tp], qh_f[tp], kl_f, accS[tp]);
                wmma::mma_sync(accS[tp], ql_f[tp], kh_f, accS[tp]);
            }
        }
        if (ch < 7) {   // store next chunk into OTHER buffer (conv-proven pattern)
            bf16* nb = smb + QB0 + ((ch + 1) & 1) * 4608;
            __align__(16) bf16 hh[8], ll[8];
#pragma unroll
            for (int j = 0; j < 8; j++) {
                const float q = qv[j] * aq + cq0;
                hh[j] = __float2bfloat16_rn(q);
                ll[j] = __float2bfloat16_rn(q - __bfloat162float(hh[j]));
            }
            *(uint4*)&nb[cl * 72 + il * 8]        = *(uint4*)hh;
            *(uint4*)&nb[2304 + cl * 72 + il * 8] = *(uint4*)ll;
        }
        __syncthreads();
    }
#pragma unroll
    for (int tp = 0; tp < 2; tp++)
        wmma::store_matrix_sync(Sf + (warp_p * 32 + tp * 16) * 68 + warp_pp * 16,
                                accS[tp], 68, wmma::mem_row_major);
    __syncthreads();

    // ---- phase 3: row softmax on Sf (proven; 256 thr = 4 lanes/row) ----
    {
        float* row = Sf + (tid >> 2) * 68 + (tid & 3) * 16;
        float mx = -1e30f;
#pragma unroll
        for (int j = 0; j < 16; j++) mx = fmaxf(mx, row[j] * 0.0625f);
        mx = fmaxf(mx, __shfl_xor_sync(0xffffffffu, mx, 1));
        mx = fmaxf(mx, __shfl_xor_sync(0xffffffffu, mx, 2));
        float s = 0.f;
#pragma unroll
        for (int j = 0; j < 16; j++) { float e = __expf(row[j] * 0.0625f - mx); row[j] = e; s += e; }
        s += __shfl_xor_sync(0xffffffffu, s, 1);
        s += __shfl_xor_sync(0xffffffffu, s, 2);
        const float inv = 1.0f / s;
#pragma unroll
        for (int j = 0; j < 16; j++) row[j] *= inv;
    }
    __syncthreads();

    // ---- phase 4: A -> bf16 hi/lo [p][72] (overlays q buffers) ----
    {
        const int p = tid >> 2, s16 = (tid & 3) * 16;
        const float* src = Sf + p * 68 + s16;
        __align__(16) bf16 hh[16], ll[16];
#pragma unroll
        for (int j = 0; j < 16; j++) {
            const float v = src[j];
            hh[j] = __float2bfloat16_rn(v);
            ll[j] = __float2bfloat16_rn(v - __bfloat162float(hh[j]));
        }
        *(uint4*)&smb[AHI + p * 72 + s16]     = *(uint4*)&hh[0];
        *(uint4*)&smb[AHI + p * 72 + s16 + 8] = *(uint4*)&hh[8];
        *(uint4*)&smb[ALO + p * 72 + s16]     = *(uint4*)&ll[0];
        *(uint4*)&smb[ALO + p * 72 + s16 + 8] = *(uint4*)&ll[8];
    }
    __syncthreads();

    // ---- phase 5: O = A k^T in 4 c-quarters, staged through Sf as Ostg[c][p] ----
    const int warp_p5 = wid & 3, warp_c5 = wid >> 2;
    float* Ostg = Sf;
#pragma unroll 1
    for (int qtr = 0; qtr < 4; qtr++) {
        const int c0 = qtr * 64;
        FragC accO[2];
        wmma::fill_fragment(accO[0], 0.f);
        wmma::fill_fragment(accO[1], 0.f);
#pragma unroll
        for (int ps = 0; ps < 64; ps += 16) {
            FragA ah_f, al_f;
            wmma::load_matrix_sync(ah_f, smb + AHI + warp_p5 * 16 * 72 + ps, 72);
            wmma::load_matrix_sync(al_f, smb + ALO + warp_p5 * 16 * 72 + ps, 72);
#pragma unroll
            for (int t = 0; t < 2; t++) {
                FragBc kh_f, kl_f;
                const int crow = c0 + warp_c5 * 32 + t * 16;
                wmma::load_matrix_sync(kh_f, smb + KHI + crow * 72 + ps, 72);
                wmma::load_matrix_sync(kl_f, smb + KLO + crow * 72 + ps, 72);
                wmma::mma_sync(accO[t], ah_f, kh_f, accO[t]);
                wmma::mma_sync(accO[t], ah_f, kl_f, accO[t]);
                wmma::mma_sync(accO[t], al_f, kh_f, accO[t]);
            }
        }
#pragma unroll
        for (int t = 0; t < 2; t++)
            wmma::store_matrix_sync(Ostg + (warp_c5 * 32 + t * 16) * 68 + warp_p5 * 16,
                                    accO[t], 68, wmma::mem_col_major);
        __syncthreads();

        // writeback this quarter (64 c x 64 p) with residual
#pragma unroll
        for (int r = 0; r < 4; r++) {
            const int u = tid + 256 * r;               // 0..1023
            const int cll = u >> 4, i = (u >> 1) & 7, jh = u & 1;
            const int c = c0 + cll;
            const size_t off = pbase + (size_t)c * HW_ + (size_t)i * W_ + jh * 4;
            float4 o4 = *(const float4*)&Ostg[cll * 68 + i * 8 + jh * 4];
            float4 xl = *(const float4*)(xlow + off);
            *(float4*)(out + off) = make_float4(o4.x + xl.x, o4.y + xl.y,
                                                o4.z + xl.z, o4.w + xl.w);
        }
        __syncthreads();
    }
}

// ---------------------------------------------------------------------------
// Launch
// ---------------------------------------------------------------------------
extern "C" void kernel_launch(void* const* d_in, const int* in_sizes, int n_in,
                              void* d_out, int out_size)
{
    const float* x_low  = (const float*)d_in[0];
    const float* x_high = (const float*)d_in[1];
    const float* Wq     = (const float*)d_in[2];
    const float* gq     = (const float*)d_in[3];
    const float* bq     = (const float*)d_in[4];
    const float* Wk     = (const float*)d_in[5];
    const float* gk     = (const float*)d_in[6];
    const float* bk     = (const float*)d_in[7];
    float* out = (float*)d_out;

    cudaFuncSetAttribute(conv_tc_kernel, cudaFuncAttributeMaxDynamicSharedMemorySize, CONV_SMEM);
    cudaFuncSetAttribute(attn_kernel, cudaFuncAttributeMaxDynamicSharedMemorySize, ATTN_SMEM);

    init_kernel<<<1, 1024>>>();
    wprep_kernel<<<512, 256>>>(Wq, Wk);

    conv_tc_kernel<<<dim3(2, 128, 16), 512, CONV_SMEM>>>(x_low, x_high);
    gn_finalize<<<1, 512>>>();
    attn_kernel<<<2048, 256, ATTN_SMEM>>>(x_low, gq, bq, gk, bk, out);
}